// round 1
// baseline (speedup 1.0000x reference)
#include <cuda_runtime.h>

// NormmaxBisect: alpha=1.5, 50 bisection iterations over last dim (d=2048).
// Key optimization: only elements with x > rowmax - 1 can ever be active
// (tau_m > tau_lo_init = max-1 for all iterations), so compact the active
// set (~13 elements typical for N(0,1) rows) into shared memory and run the
// 50 iterations over that tiny set. Kernel becomes HBM-bound (1 GB traffic).

#define D    2048
#define TPB  128
#define V4   4          // float4 chunks per thread: D / (TPB*4) = 4

__global__ __launch_bounds__(TPB, 16)
void normmax_bisect_kernel(const float* __restrict__ X, float* __restrict__ Y) {
    __shared__ float s_act[D];          // compacted active values (worst case = D)
    __shared__ int   s_wsum[TPB / 32];  // per-warp active counts (inclusive)
    __shared__ float s_wmax[TPB / 32];
    __shared__ float s_tau, s_inv;

    const size_t row = blockIdx.x;
    const float4* xr = reinterpret_cast<const float4*>(X + row * (size_t)D);
    float4*       yr = reinterpret_cast<float4*>(Y + row * (size_t)D);
    const int tid  = threadIdx.x;
    const int lane = tid & 31;
    const int wid  = tid >> 5;

    // ---- load row into registers (coalesced float4), local max ----
    float4 v[V4];
    float mx = -3.402823466e38f;
#pragma unroll
    for (int k = 0; k < V4; k++) {
        v[k] = xr[k * TPB + tid];
        mx = fmaxf(mx, fmaxf(fmaxf(v[k].x, v[k].y), fmaxf(v[k].z, v[k].w)));
    }
#pragma unroll
    for (int o = 16; o; o >>= 1)
        mx = fmaxf(mx, __shfl_xor_sync(0xffffffffu, mx, o));
    if (lane == 0) s_wmax[wid] = mx;
    __syncthreads();
    mx = fmaxf(fmaxf(s_wmax[0], s_wmax[1]), fmaxf(s_wmax[2], s_wmax[3]));

    const float thresh = mx - 1.0f;   // = tau_lo_init; anything <= this is dead forever

    // ---- count actives per thread, deterministic ordered compaction ----
    int lcnt = 0;
#pragma unroll
    for (int k = 0; k < V4; k++) {
        lcnt += (v[k].x > thresh) + (v[k].y > thresh) +
                (v[k].z > thresh) + (v[k].w > thresh);
    }
    // warp inclusive scan
    int scan = lcnt;
#pragma unroll
    for (int o = 1; o < 32; o <<= 1) {
        int n = __shfl_up_sync(0xffffffffu, scan, o);
        if (lane >= o) scan += n;
    }
    if (lane == 31) s_wsum[wid] = scan;
    __syncthreads();
    int base = scan - lcnt;
#pragma unroll
    for (int w = 0; w < TPB / 32; w++)
        if (w < wid) base += s_wsum[w];
    const int cnt = s_wsum[0] + s_wsum[1] + s_wsum[2] + s_wsum[3];

    {
        int p = base;
#pragma unroll
        for (int k = 0; k < V4; k++) {
            if (v[k].x > thresh) s_act[p++] = v[k].x;
            if (v[k].y > thresh) s_act[p++] = v[k].y;
            if (v[k].z > thresh) s_act[p++] = v[k].z;
            if (v[k].w > thresh) s_act[p++] = v[k].w;
        }
    }
    __syncthreads();

    // ---- thread 0: 50 bisection iterations over the compact active set ----
    if (tid == 0) {
        float tau_lo = mx - 1.0f;
        // dm0 = tau_hi - tau_lo, computed exactly like the reference:
        // tau_hi = max - (1/d)^(alpha-1) = max - (1/2048)^0.5
        float dm  = (mx - 0.02209708691207961f) - tau_lo;
        float tau = tau_lo;
#pragma unroll 1
        for (int it = 0; it < 50; it++) {
            dm *= 0.5f;
            tau = tau_lo + dm;
            float f0 = 0.f, f1 = 0.f, f2 = 0.f, f3 = 0.f;
            int i = 0;
            for (; i + 4 <= cnt; i += 4) {
                float t0 = fmaxf(s_act[i + 0] - tau, 0.f);
                float t1 = fmaxf(s_act[i + 1] - tau, 0.f);
                float t2 = fmaxf(s_act[i + 2] - tau, 0.f);
                float t3 = fmaxf(s_act[i + 3] - tau, 0.f);
                f0 = fmaf(t0 * t0, t0, f0);
                f1 = fmaf(t1 * t1, t1, f1);
                f2 = fmaf(t2 * t2, t2, f2);
                f3 = fmaf(t3 * t3, t3, f3);
            }
            for (; i < cnt; i++) {
                float t = fmaxf(s_act[i] - tau, 0.f);
                f0 = fmaf(t * t, t, f0);
            }
            // f_m = sum(p^alpha) - 1 >= 0  <=>  sum(t^3) >= 1
            if ((f0 + f1) + (f2 + f3) >= 1.0f) tau_lo = tau;
        }
        // p_m from the LAST iteration's tau_m; final renormalization sum
        float s = 0.f;
        for (int i = 0; i < cnt; i++) {
            float t = fmaxf(s_act[i] - tau, 0.f);
            s = fmaf(t, t, s);
        }
        s_tau = tau;
        s_inv = 1.0f / s;
    }
    __syncthreads();

    // ---- emit normalized p from register-held x ----
    const float tau = s_tau;
    const float inv = s_inv;
#pragma unroll
    for (int k = 0; k < V4; k++) {
        float4 o;
        float t;
        t = fmaxf(v[k].x - tau, 0.f); o.x = t * t * inv;
        t = fmaxf(v[k].y - tau, 0.f); o.y = t * t * inv;
        t = fmaxf(v[k].z - tau, 0.f); o.z = t * t * inv;
        t = fmaxf(v[k].w - tau, 0.f); o.w = t * t * inv;
        yr[k * TPB + tid] = o;
    }
}

extern "C" void kernel_launch(void* const* d_in, const int* in_sizes, int n_in,
                              void* d_out, int out_size) {
    const float* X = (const float*)d_in[0];
    float*       Y = (float*)d_out;
    const int rows = in_sizes[0] / D;   // 2*16*2048 = 65536
    normmax_bisect_kernel<<<rows, TPB>>>(X, Y);
}

// round 2
// speedup vs baseline: 2.7783x; 2.7783x over previous
#include <cuda_runtime.h>

// NormmaxBisect: alpha=1.5, bisection over last dim (d=2048).
// R1 finding: bisection on thread0/warp0 piled all serial work onto SMSP 0.
// R2: (a) bisection warp = blockIdx&3 (spread across SMSPs),
//     (b) lane-parallel bisection (1 active value per lane + shfl butterfly),
//     (c) 36 iterations (fp32 tau freezes by ~iter 25; identical result to 50).

#define D      2048
#define TPB    128
#define V4     4      // float4 chunks per thread: D / (TPB*4) = 4
#define NITER  36

__global__ __launch_bounds__(TPB, 12)
void normmax_bisect_kernel(const float* __restrict__ X, float* __restrict__ Y) {
    __shared__ float s_act[D];          // compacted active values (worst case D)
    __shared__ int   s_wsum[TPB / 32];
    __shared__ float s_wmax[TPB / 32];
    __shared__ float s_res[2];          // {tau, 1/sum}

    const size_t row = blockIdx.x;
    const float4* xr = reinterpret_cast<const float4*>(X + row * (size_t)D);
    float4*       yr = reinterpret_cast<float4*>(Y + row * (size_t)D);
    const int tid  = threadIdx.x;
    const int lane = tid & 31;
    const int wid  = tid >> 5;

    // ---- load row into registers (coalesced float4), block max ----
    float4 v[V4];
    float mx = -3.402823466e38f;
#pragma unroll
    for (int k = 0; k < V4; k++) {
        v[k] = xr[k * TPB + tid];
        mx = fmaxf(mx, fmaxf(fmaxf(v[k].x, v[k].y), fmaxf(v[k].z, v[k].w)));
    }
#pragma unroll
    for (int o = 16; o; o >>= 1)
        mx = fmaxf(mx, __shfl_xor_sync(0xffffffffu, mx, o));
    if (lane == 0) s_wmax[wid] = mx;
    __syncthreads();
    mx = fmaxf(fmaxf(s_wmax[0], s_wmax[1]), fmaxf(s_wmax[2], s_wmax[3]));

    const float thresh = mx - 1.0f;   // tau_m > max-1 always => x<=max-1 contributes 0 forever

    // ---- ordered compaction of active values into smem ----
    int lcnt = 0;
#pragma unroll
    for (int k = 0; k < V4; k++) {
        lcnt += (v[k].x > thresh) + (v[k].y > thresh) +
                (v[k].z > thresh) + (v[k].w > thresh);
    }
    int scan = lcnt;
#pragma unroll
    for (int o = 1; o < 32; o <<= 1) {
        int n = __shfl_up_sync(0xffffffffu, scan, o);
        if (lane >= o) scan += n;
    }
    if (lane == 31) s_wsum[wid] = scan;
    __syncthreads();
    int base = scan - lcnt;
#pragma unroll
    for (int w = 0; w < TPB / 32; w++)
        if (w < wid) base += s_wsum[w];
    const int cnt = s_wsum[0] + s_wsum[1] + s_wsum[2] + s_wsum[3];

    {
        int p = base;
#pragma unroll
        for (int k = 0; k < V4; k++) {
            if (v[k].x > thresh) s_act[p++] = v[k].x;
            if (v[k].y > thresh) s_act[p++] = v[k].y;
            if (v[k].z > thresh) s_act[p++] = v[k].z;
            if (v[k].w > thresh) s_act[p++] = v[k].w;
        }
    }
    __syncthreads();

    // ---- lane-parallel bisection on one warp; warp index rotates per block
    //      so the serial phase spreads across all 4 SMSPs ----
    if (wid == (int)(blockIdx.x & 3)) {
        float tau_lo = mx - 1.0f;
        // dm0 = tau_hi - tau_lo, tau_hi = max - (1/2048)^0.5
        float dm  = (mx - 0.02209708691207961f) - tau_lo;
        float tau = tau_lo;

        if (cnt <= 32) {                       // common case (~13 actives)
            float a = (lane < cnt) ? s_act[lane] : -3.402823466e38f;
#pragma unroll 1
            for (int it = 0; it < NITER; it++) {
                dm *= 0.5f;
                tau = tau_lo + dm;
                float t = fmaxf(a - tau, 0.f);
                float f = t * t * t;
#pragma unroll
                for (int o = 16; o; o >>= 1)
                    f += __shfl_xor_sync(0xffffffffu, f, o);
                if (f >= 1.0f) tau_lo = tau;   // uniform across lanes
            }
            float t = fmaxf(a - tau, 0.f);
            float s = t * t;
#pragma unroll
            for (int o = 16; o; o >>= 1)
                s += __shfl_xor_sync(0xffffffffu, s, o);
            if (lane == 0) { s_res[0] = tau; s_res[1] = 1.0f / s; }
        } else {                               // rare: cnt > 32, stride smem
#pragma unroll 1
            for (int it = 0; it < NITER; it++) {
                dm *= 0.5f;
                tau = tau_lo + dm;
                float f = 0.f;
                for (int i = lane; i < cnt; i += 32) {
                    float t = fmaxf(s_act[i] - tau, 0.f);
                    f = fmaf(t * t, t, f);
                }
#pragma unroll
                for (int o = 16; o; o >>= 1)
                    f += __shfl_xor_sync(0xffffffffu, f, o);
                if (f >= 1.0f) tau_lo = tau;
            }
            float s = 0.f;
            for (int i = lane; i < cnt; i += 32) {
                float t = fmaxf(s_act[i] - tau, 0.f);
                s = fmaf(t, t, s);
            }
#pragma unroll
            for (int o = 16; o; o >>= 1)
                s += __shfl_xor_sync(0xffffffffu, s, o);
            if (lane == 0) { s_res[0] = tau; s_res[1] = 1.0f / s; }
        }
    }
    __syncthreads();

    // ---- emit normalized p from register-held x ----
    const float tau = s_res[0];
    const float inv = s_res[1];
#pragma unroll
    for (int k = 0; k < V4; k++) {
        float4 o;
        float t;
        t = fmaxf(v[k].x - tau, 0.f); o.x = t * t * inv;
        t = fmaxf(v[k].y - tau, 0.f); o.y = t * t * inv;
        t = fmaxf(v[k].z - tau, 0.f); o.z = t * t * inv;
        t = fmaxf(v[k].w - tau, 0.f); o.w = t * t * inv;
        yr[k * TPB + tid] = o;
    }
}

extern "C" void kernel_launch(void* const* d_in, const int* in_sizes, int n_in,
                              void* d_out, int out_size) {
    const float* X = (const float*)d_in[0];
    float*       Y = (float*)d_out;
    const int rows = in_sizes[0] / D;   // 65536
    normmax_bisect_kernel<<<rows, TPB>>>(X, Y);
}

// round 4
// speedup vs baseline: 3.7289x; 1.3421x over previous
#include <cuda_runtime.h>

// NormmaxBisect: alpha=1.5 normmax over last dim (d=2048).
// R3 failed: redux.sync.add.f32 doesn't exist on sm_103 (sm_100a-only).
// R4: Newton (12 iters) on f(tau)=sum(max(x-tau,0)^3)-1 with DUAL INTERLEAVED
// shfl butterflies: the Sigma t^2 and Sigma t^3 reductions are independent, so
// their 5-step butterflies pipeline (~140cy, ~= one chain). Serial chain
// ~2300cy vs R2's ~5800cy. Active-set pruning + SMSP-rotating solver warp kept.

#define D       2048
#define TPB     128
#define V4      4      // float4 chunks per thread: D / (TPB*4) = 4
#define NEWTON  12

__global__ __launch_bounds__(TPB, 12)
void normmax_bisect_kernel(const float* __restrict__ X, float* __restrict__ Y) {
    __shared__ float s_act[D];          // compacted active values (worst case D)
    __shared__ int   s_wsum[TPB / 32];
    __shared__ float s_wmax[TPB / 32];
    __shared__ float s_res[2];          // {tau, 1/sum}

    const size_t row = blockIdx.x;
    const float4* xr = reinterpret_cast<const float4*>(X + row * (size_t)D);
    float4*       yr = reinterpret_cast<float4*>(Y + row * (size_t)D);
    const int tid  = threadIdx.x;
    const int lane = tid & 31;
    const int wid  = tid >> 5;

    // ---- load row into registers (coalesced float4), block max ----
    float4 v[V4];
    float mx = -3.402823466e38f;
#pragma unroll
    for (int k = 0; k < V4; k++) {
        v[k] = xr[k * TPB + tid];
        mx = fmaxf(mx, fmaxf(fmaxf(v[k].x, v[k].y), fmaxf(v[k].z, v[k].w)));
    }
#pragma unroll
    for (int o = 16; o; o >>= 1)
        mx = fmaxf(mx, __shfl_xor_sync(0xffffffffu, mx, o));
    if (lane == 0) s_wmax[wid] = mx;
    __syncthreads();
    mx = fmaxf(fmaxf(s_wmax[0], s_wmax[1]), fmaxf(s_wmax[2], s_wmax[3]));

    const float thresh = mx - 1.0f;  // tau >= max-1 always => x<=max-1 dead forever

    // ---- ordered compaction of active values into smem ----
    int lcnt = 0;
#pragma unroll
    for (int k = 0; k < V4; k++) {
        lcnt += (v[k].x > thresh) + (v[k].y > thresh) +
                (v[k].z > thresh) + (v[k].w > thresh);
    }
    int scan = lcnt;
#pragma unroll
    for (int o = 1; o < 32; o <<= 1) {
        int n = __shfl_up_sync(0xffffffffu, scan, o);
        if (lane >= o) scan += n;
    }
    if (lane == 31) s_wsum[wid] = scan;
    __syncthreads();
    int base = scan - lcnt;
#pragma unroll
    for (int w = 0; w < TPB / 32; w++)
        if (w < wid) base += s_wsum[w];
    const int cnt = s_wsum[0] + s_wsum[1] + s_wsum[2] + s_wsum[3];

    {
        int p = base;
#pragma unroll
        for (int k = 0; k < V4; k++) {
            if (v[k].x > thresh) s_act[p++] = v[k].x;
            if (v[k].y > thresh) s_act[p++] = v[k].y;
            if (v[k].z > thresh) s_act[p++] = v[k].z;
            if (v[k].w > thresh) s_act[p++] = v[k].w;
        }
    }
    __syncthreads();

    // ---- Newton solve on one warp; warp index rotates per block so the
    //      serial phase spreads across all 4 SMSPs ----
    if (wid == (int)(blockIdx.x & 3)) {
        float tau = mx - 1.0f;   // f(tau0) >= 0 (t_max = 1)

        if (cnt <= 32) {                       // common case (~13 actives)
            float a = (lane < cnt) ? s_act[lane] : -3.402823466e38f;
#pragma unroll 1
            for (int it = 0; it < NEWTON; it++) {
                float t  = fmaxf(a - tau, 0.f);
                float t2 = t * t;
                float f2 = t2;
                float f3 = t2 * t;
#pragma unroll
                for (int o = 16; o; o >>= 1) {   // dual butterfly, pipelined
                    f3 += __shfl_xor_sync(0xffffffffu, f3, o);
                    f2 += __shfl_xor_sync(0xffffffffu, f2, o);
                }
                tau += (f3 - 1.0f) / (3.0f * f2);
            }
            float t = fmaxf(a - tau, 0.f);
            float s = t * t;
#pragma unroll
            for (int o = 16; o; o >>= 1)
                s += __shfl_xor_sync(0xffffffffu, s, o);
            if (lane == 0) { s_res[0] = tau; s_res[1] = 1.0f / s; }
        } else {                               // rare: cnt > 32, stride smem
#pragma unroll 1
            for (int it = 0; it < NEWTON + 4; it++) {
                float f2 = 0.f, f3 = 0.f;
                for (int i = lane; i < cnt; i += 32) {
                    float t  = fmaxf(s_act[i] - tau, 0.f);
                    float t2 = t * t;
                    f2 += t2;
                    f3 = fmaf(t2, t, f3);
                }
#pragma unroll
                for (int o = 16; o; o >>= 1) {
                    f3 += __shfl_xor_sync(0xffffffffu, f3, o);
                    f2 += __shfl_xor_sync(0xffffffffu, f2, o);
                }
                tau += (f3 - 1.0f) / (3.0f * f2);
            }
            float s = 0.f;
            for (int i = lane; i < cnt; i += 32) {
                float t = fmaxf(s_act[i] - tau, 0.f);
                s = fmaf(t, t, s);
            }
#pragma unroll
            for (int o = 16; o; o >>= 1)
                s += __shfl_xor_sync(0xffffffffu, s, o);
            if (lane == 0) { s_res[0] = tau; s_res[1] = 1.0f / s; }
        }
    }
    __syncthreads();

    // ---- emit normalized p from register-held x ----
    const float tau = s_res[0];
    const float inv = s_res[1];
#pragma unroll
    for (int k = 0; k < V4; k++) {
        float4 o;
        float t;
        t = fmaxf(v[k].x - tau, 0.f); o.x = t * t * inv;
        t = fmaxf(v[k].y - tau, 0.f); o.y = t * t * inv;
        t = fmaxf(v[k].z - tau, 0.f); o.z = t * t * inv;
        t = fmaxf(v[k].w - tau, 0.f); o.w = t * t * inv;
        yr[k * TPB + tid] = o;
    }
}

extern "C" void kernel_launch(void* const* d_in, const int* in_sizes, int n_in,
                              void* d_out, int out_size) {
    const float* X = (const float*)d_in[0];
    float*       Y = (float*)d_out;
    const int rows = in_sizes[0] / D;   // 65536
    normmax_bisect_kernel<<<rows, TPB>>>(X, Y);
}

// round 5
// speedup vs baseline: 3.7744x; 1.0122x over previous
#include <cuda_runtime.h>

// NormmaxBisect: alpha=1.5 normmax over last dim (d=2048).
// R4 finding: regs=40 capped occupancy at 12 blocks/SM (71%), DRAM stuck 64%.
// R5: row lives in SMEM (8KB) instead of 16 registers/thread; active array
// shrunk to 192 entries (cnt>192 falls back to striding the full smem row,
// clamp prunes); __launch_bounds__(128,16) -> 32 regs -> 16 blocks = 100% occ.
// Newton(12) solve with dual interleaved shfl butterflies unchanged from R4.

#define D       2048
#define TPB     128
#define CAP     192
#define NEWTON  12

__device__ __forceinline__ void stcs(float4* p, float4 v) {
    asm volatile("st.global.cs.v4.f32 [%0], {%1,%2,%3,%4};"
                 :: "l"(p), "f"(v.x), "f"(v.y), "f"(v.z), "f"(v.w) : "memory");
}

__global__ __launch_bounds__(TPB, 16)
void normmax_bisect_kernel(const float* __restrict__ X, float* __restrict__ Y) {
    __shared__ float s_row[D];          // full row (8KB)
    __shared__ float s_act[CAP];        // compacted actives (typ ~13)
    __shared__ int   s_wsum[TPB / 32];
    __shared__ float s_wmax[TPB / 32];
    __shared__ float s_res[2];          // {tau, 1/sum}

    const size_t row = blockIdx.x;
    const float4* xr = reinterpret_cast<const float4*>(X + row * (size_t)D);
    float4*       yr = reinterpret_cast<float4*>(Y + row * (size_t)D);
    float4*       s4 = reinterpret_cast<float4*>(s_row);
    const int tid  = threadIdx.x;
    const int lane = tid & 31;
    const int wid  = tid >> 5;

    // ---- phase 1: X -> smem (single DRAM read), block max ----
    float mx = -3.402823466e38f;
#pragma unroll
    for (int k = 0; k < 4; k++) {
        float4 t = xr[k * TPB + tid];
        s4[k * TPB + tid] = t;
        mx = fmaxf(mx, fmaxf(fmaxf(t.x, t.y), fmaxf(t.z, t.w)));
    }
#pragma unroll
    for (int o = 16; o; o >>= 1)
        mx = fmaxf(mx, __shfl_xor_sync(0xffffffffu, mx, o));
    if (lane == 0) s_wmax[wid] = mx;
    __syncthreads();                     // also publishes s_row
    mx = fmaxf(fmaxf(s_wmax[0], s_wmax[1]), fmaxf(s_wmax[2], s_wmax[3]));
    const float thresh = mx - 1.0f;      // tau >= max-1 forever => x<=max-1 dead

    // ---- phase 2: count actives (pass A), scan, compact (pass B) ----
    int lcnt = 0;
#pragma unroll
    for (int k = 0; k < 4; k++) {
        float4 t = s4[k * TPB + tid];
        lcnt += (t.x > thresh) + (t.y > thresh) + (t.z > thresh) + (t.w > thresh);
    }
    int scan = lcnt;
#pragma unroll
    for (int o = 1; o < 32; o <<= 1) {
        int n = __shfl_up_sync(0xffffffffu, scan, o);
        if (lane >= o) scan += n;
    }
    if (lane == 31) s_wsum[wid] = scan;
    __syncthreads();
    int base = scan - lcnt;
#pragma unroll
    for (int w = 0; w < TPB / 32; w++)
        if (w < wid) base += s_wsum[w];
    const int cnt = s_wsum[0] + s_wsum[1] + s_wsum[2] + s_wsum[3];

    if (cnt <= CAP) {                    // overflow => solver strides s_row
        int p = base;
#pragma unroll
        for (int k = 0; k < 4; k++) {
            float4 t = s4[k * TPB + tid];
            if (t.x > thresh) s_act[p++] = t.x;
            if (t.y > thresh) s_act[p++] = t.y;
            if (t.z > thresh) s_act[p++] = t.z;
            if (t.w > thresh) s_act[p++] = t.w;
        }
    }
    __syncthreads();

    // ---- phase 3: Newton on one warp (rotates across SMSPs per block) ----
    // f(tau) = sum(max(x-tau,0)^3) - 1: convex, decreasing, f(max-1) >= 0
    // => monotone quadratic convergence from tau0 = max-1.
    if (wid == (int)(blockIdx.x & 3)) {
        float tau = mx - 1.0f;
        if (cnt <= 32) {                       // common case (~13 actives)
            float a = (lane < cnt) ? s_act[lane] : -3.402823466e38f;
#pragma unroll 1
            for (int it = 0; it < NEWTON; it++) {
                float t  = fmaxf(a - tau, 0.f);
                float t2 = t * t;
                float f2 = t2;
                float f3 = t2 * t;
#pragma unroll
                for (int o = 16; o; o >>= 1) {  // dual butterfly, pipelined
                    f3 += __shfl_xor_sync(0xffffffffu, f3, o);
                    f2 += __shfl_xor_sync(0xffffffffu, f2, o);
                }
                tau += (f3 - 1.0f) / (3.0f * f2);
            }
            float t = fmaxf(a - tau, 0.f);
            float s = t * t;
#pragma unroll
            for (int o = 16; o; o >>= 1)
                s += __shfl_xor_sync(0xffffffffu, s, o);
            if (lane == 0) { s_res[0] = tau; s_res[1] = 1.0f / s; }
        } else {                               // rare: stride smem
            const float* src = (cnt <= CAP) ? s_act : s_row;
            const int    n   = (cnt <= CAP) ? cnt   : D;
#pragma unroll 1
            for (int it = 0; it < NEWTON + 4; it++) {
                float f2 = 0.f, f3 = 0.f;
                for (int i = lane; i < n; i += 32) {
                    float t  = fmaxf(src[i] - tau, 0.f);
                    float t2 = t * t;
                    f2 += t2;
                    f3 = fmaf(t2, t, f3);
                }
#pragma unroll
                for (int o = 16; o; o >>= 1) {
                    f3 += __shfl_xor_sync(0xffffffffu, f3, o);
                    f2 += __shfl_xor_sync(0xffffffffu, f2, o);
                }
                tau += (f3 - 1.0f) / (3.0f * f2);
            }
            float f2 = 0.f;
            for (int i = lane; i < n; i += 32) {
                float t = fmaxf(src[i] - tau, 0.f);
                f2 = fmaf(t, t, f2);
            }
#pragma unroll
            for (int o = 16; o; o >>= 1)
                f2 += __shfl_xor_sync(0xffffffffu, f2, o);
            if (lane == 0) { s_res[0] = tau; s_res[1] = 1.0f / f2; }
        }
    }
    __syncthreads();

    // ---- phase 4: emit normalized p from smem row (streaming stores) ----
    const float tau = s_res[0];
    const float inv = s_res[1];
#pragma unroll
    for (int k = 0; k < 4; k++) {
        float4 t = s4[k * TPB + tid];
        float4 o;
        float u;
        u = fmaxf(t.x - tau, 0.f); o.x = u * u * inv;
        u = fmaxf(t.y - tau, 0.f); o.y = u * u * inv;
        u = fmaxf(t.z - tau, 0.f); o.z = u * u * inv;
        u = fmaxf(t.w - tau, 0.f); o.w = u * u * inv;
        stcs(yr + k * TPB + tid, o);
    }
}

extern "C" void kernel_launch(void* const* d_in, const int* in_sizes, int n_in,
                              void* d_out, int out_size) {
    const float* X = (const float*)d_in[0];
    float*       Y = (float*)d_out;
    const int rows = in_sizes[0] / D;   // 65536
    normmax_bisect_kernel<<<rows, TPB>>>(X, Y);
}